// round 14
// baseline (speedup 1.0000x reference)
#include <cuda_runtime.h>
#include <math.h>

typedef unsigned long long ull;

#define TT   512
#define BBAT 64
#define DD   128
#define UU   256
#define G3   768
#define NBLK 128
#define TPB  256
#define CH   8
#define GBLK 8            // blocks per group == cluster size
#define WROW 260          // Wc row stride in floats
#define AROW 260          // Ab row stride in floats

// ---------------- device scratch ----------------
__device__ float g_xg[(size_t)BBAT * TT * G3];   // x @ W_in + bias0
__device__ float g_basep[2][BBAT][CH][UU];       // chunk-base partials (2 j-halves)

// packed f32x2 helpers (Blackwell; ptxas never emits FFMA2 from C++)
#define FMA2(acc, a, b) \
    asm("fma.rn.f32x2 %0, %1, %2, %0;" : "+l"(acc) : "l"(a), "l"(b))
#define ADD2(acc, a) \
    asm("add.rn.f32x2 %0, %1, %0;" : "+l"(acc) : "l"(a))
__device__ __forceinline__ void unpack2(ull v, float& x, float& y) {
    asm("mov.b64 {%0, %1}, %2;" : "=f"(x), "=f"(y) : "l"(v));
}
__device__ __forceinline__ float tanh_fast(float v) {
    float y; asm("tanh.approx.f32 %0, %1;" : "=f"(y) : "f"(v)); return y;
}

// HW cluster barrier. Group == CGA (all cross-block traffic is intra-cluster
// by construction), so arrive.aligned's RELEASE + wait.aligned's ACQUIRE at
// cluster scope order our global-memory (L2) producer->consumer flows —
// no __threadfence needed. Gang scheduling guarantees co-residency; groups
// never sync with each other, so clusters drift freely.
__device__ __forceinline__ void cluster_sync() {
    asm volatile("barrier.cluster.arrive.aligned;" ::: "memory");
    asm volatile("barrier.cluster.wait.aligned;" ::: "memory");
}

// smem layout (float offsets)
#define WC_OFF   0        // Wc: 96 cols x 260 f (col-major, k contiguous) = 24960 f
#define AB_OFF   24960    // Ab: 4 batches x 260 f (next_state rows)
#define BIG_OFF  26000    // 8192 f union: stage0 As / chunk Hs
#define CS_OFF   34192    // 256 f chunk cond tile
#define CSM_OFF  34448    // 64 f per-step cond stage (double-buffered 2x32)
#define GH_OFF   34512    // 384 f h-side preactivations [4][96]
#define SMEM_F   34896    // 139584 B

__global__ void __launch_bounds__(TPB, 1) __cluster_dims__(GBLK, 1, 1)
dag_rnn_kernel(
    const float* __restrict__ x,     // (B,T,D)
    const float* __restrict__ cond,  // (B,T,T)
    const float* __restrict__ Win,   // (D,3U)
    const float* __restrict__ Wrec,  // (U,3U)
    const float* __restrict__ bias,  // (2,3U)
    float* __restrict__ out)         // (B,T,U) == H storage
{
    extern __shared__ __align__(16) float smem[];
    float* Wc  = smem + WC_OFF;           // [cc][k], stride WROW
    float* Ab  = smem + AB_OFF;           // [bb][k], stride AROW
    float* BIG = smem + BIG_OFF;
    float* Cs  = smem + CS_OFF;
    float* Csm = smem + CSM_OFF;          // 2 x 32
    float* Gh  = smem + GH_OFF;           // [bb][cc]

    const int tid = threadIdx.x;
    const int blk = blockIdx.x;
    const int gid = blk >> 3;          // group == cluster (4 batches)
    const int s   = blk & 7;           // u-slice within group

    const int b0 = gid * 4;            // first batch of group
    const int us = 32 * s;             // u-slice origin

    // GEMM identity (tid<192): bq = batch-pair (0/1), cc = column 0..95
    const int cc = tid % 96;
    const int bq = tid / 96;
    const int gcol = (cc >> 5) * UU + us + (cc & 31);
    float bh = 0.f;
    if (tid < 192) bh = bias[G3 + gcol];

    // ---- preload Wrec slice col-major: Wc[cc*WROW + k] ----
    for (int idx = tid; idx < 96 * UU; idx += TPB) {
        int ccc = idx >> 8, k = idx & 255;
        int colc = (ccc >> 5) * UU + us + (ccc & 31);
        Wc[ccc * WROW + k] = Wrec[(size_t)k * G3 + colc];
    }

    // ================= stage 0: g_xg = x @ Win + bias0 =================
    {
        float* As = BIG;                       // 32 x 128
        const float bz  = bias[tid];
        const float br  = bias[UU + tid];
        const float bhh = bias[2 * UU + tid];
        const int row0 = blk * 256;
        for (int rt = 0; rt < 8; ++rt) {
            const int rbase = row0 + rt * 32;
            __syncthreads();
            for (int idx = tid; idx < 32 * DD; idx += TPB)
                As[idx] = x[(size_t)rbase * DD + idx];
            __syncthreads();
            for (int rs = 0; rs < 4; ++rs) {
                float a0[8], a1[8], a2[8];
                #pragma unroll
                for (int r = 0; r < 8; ++r) { a0[r] = 0.f; a1[r] = 0.f; a2[r] = 0.f; }
                const float* asr = As + (rs * 8) * DD;
                #pragma unroll 4
                for (int k = 0; k < DD; ++k) {
                    float w0 = __ldg(&Win[(size_t)k * G3 + tid]);
                    float w1 = __ldg(&Win[(size_t)k * G3 + UU + tid]);
                    float w2 = __ldg(&Win[(size_t)k * G3 + 2 * UU + tid]);
                    #pragma unroll
                    for (int r = 0; r < 8; ++r) {
                        float a = asr[r * DD + k];
                        a0[r] += a * w0; a1[r] += a * w1; a2[r] += a * w2;
                    }
                }
                #pragma unroll
                for (int r = 0; r < 8; ++r) {
                    size_t ro = (size_t)(rbase + rs * 8 + r) * G3;
                    g_xg[ro + tid]          = a0[r] + bz;
                    g_xg[ro + UU + tid]     = a1[r] + br;
                    g_xg[ro + 2 * UU + tid] = a2[r] + bhh;
                }
            }
        }
    }
    cluster_sync();

    const float invT = 1.0f / (float)TT;

    // gate-input registers (tid<128: bb = tid>>5, uq = tid&31), one step ahead
    float xz = 0.f, xr = 0.f, xh = 0.f;
    if (tid < 128) {
        const int uq = tid & 31, bb2 = tid >> 5;
        const size_t xo = ((size_t)(b0 + bb2) * TT + 0) * G3 + us + uq;
        xz = __ldg(&g_xg[xo]);
        xr = __ldg(&g_xg[xo + UU]);
        xh = __ldg(&g_xg[xo + 2 * UU]);
    }

    for (int c0 = 0; c0 < TT; c0 += CH) {
        // ---------- chunk-base GEMM: 4 group batches x 2 j-halves ----------
        if (c0 > 0) {
            float* Hs = BIG;
            const int cb   = b0 + (s >> 1);    // batch for this block
            const int jh   = s & 1;            // j-half
            const int kb   = c0 >> 1;
            const int jbeg = jh * kb;
            const float* hrow = out  + ((size_t)cb * TT + jbeg) * UU;
            const float* crow = cond + ((size_t)cb * TT + c0) * TT + jbeg;

            float acc[2][8];
            #pragma unroll
            for (int a = 0; a < 2; ++a)
                #pragma unroll
                for (int q = 0; q < 8; ++q) acc[a][q] = 0.f;

            const int lg = tid >> 5;
            const int ug = tid & 31;

            for (int jt = 0; jt < kb; jt += 32) {
                const int jn = (kb - jt < 32) ? (kb - jt) : 32;
                __syncthreads();
                for (int idx = tid; idx < jn * UU; idx += TPB)
                    Hs[idx] = __ldcg(&hrow[(size_t)jt * UU + idx]);
                {
                    int l = tid >> 5, jj = tid & 31;
                    if (jj < jn)
                        Cs[jj * CH + l] = __ldg(&crow[(size_t)l * TT + jt + jj]);
                }
                __syncthreads();
                if (tid < 128) {
                    for (int jj = 0; jj < jn; ++jj) {
                        float cv0 = Cs[jj * CH + lg];
                        float cv1 = Cs[jj * CH + lg + 4];
                        const float4* h4 = (const float4*)&Hs[jj * UU + ug * 8];
                        float4 ha = h4[0], hb2 = h4[1];
                        acc[0][0] += cv0 * ha.x;  acc[0][1] += cv0 * ha.y;
                        acc[0][2] += cv0 * ha.z;  acc[0][3] += cv0 * ha.w;
                        acc[0][4] += cv0 * hb2.x; acc[0][5] += cv0 * hb2.y;
                        acc[0][6] += cv0 * hb2.z; acc[0][7] += cv0 * hb2.w;
                        acc[1][0] += cv1 * ha.x;  acc[1][1] += cv1 * ha.y;
                        acc[1][2] += cv1 * ha.z;  acc[1][3] += cv1 * ha.w;
                        acc[1][4] += cv1 * hb2.x; acc[1][5] += cv1 * hb2.y;
                        acc[1][6] += cv1 * hb2.z; acc[1][7] += cv1 * hb2.w;
                    }
                }
            }
            if (tid < 128) {
                #pragma unroll
                for (int li = 0; li < 2; ++li) {
                    const int l = lg + li * 4;
                    float* dst = &g_basep[jh][cb][l][ug * 8];
                    ((float4*)dst)[0] = make_float4(acc[li][0], acc[li][1],
                                                    acc[li][2], acc[li][3]);
                    ((float4*)dst)[1] = make_float4(acc[li][4], acc[li][5],
                                                    acc[li][6], acc[li][7]);
                }
            }
            cluster_sync();
        }

        // ---------------- sequential steps within chunk ----------------
        for (int l = 0; l < CH; ++l) {
            const int i = c0 + l;
            const int lnext = (l < CH - 1) ? (l + 1) : 0;
            float* CsmCur = Csm + (l & 1) * 32;
            float* CsmNxt = Csm + ((l + 1) & 1) * 32;

            // ---- phase A: full next_state for 4 batches (thread = u) ----
            {
                const int u = tid;             // 0..255
                float acc[4];
                if (c0 > 0) {
                    #pragma unroll
                    for (int bb = 0; bb < 4; ++bb)
                        acc[bb] = __ldcg(&g_basep[0][b0 + bb][l][u])
                                + __ldcg(&g_basep[1][b0 + bb][l][u]);
                } else {
                    #pragma unroll
                    for (int bb = 0; bb < 4; ++bb) acc[bb] = 0.f;
                }
                for (int jj = 0; jj < l; ++jj) {
                    #pragma unroll
                    for (int bb = 0; bb < 4; ++bb) {
                        float cv = CsmCur[jj * 4 + bb];
                        acc[bb] += cv * __ldcg(
                            &out[((size_t)(b0 + bb) * TT + c0 + jj) * UU + u]);
                    }
                }
                #pragma unroll
                for (int bb = 0; bb < 4; ++bb)
                    Ab[bb * AROW + u] = acc[bb] * invT;
            }
            __syncthreads();

            // ---- prefetch next step's cond + gate inputs ----
            float cnext = 0.f, xzp = 0.f, xrp = 0.f, xhp = 0.f;
            if (tid < 128) {
                const int jj = tid >> 2, bb = tid & 3;
                if (jj < lnext)
                    cnext = __ldg(&cond[((size_t)(b0 + bb) * TT + (i + 1)) * TT
                                        + c0 + jj]);
                if (i + 1 < TT) {
                    const int uq = tid & 31, bb2 = tid >> 5;
                    const size_t xo = ((size_t)(b0 + bb2) * TT + (i + 1)) * G3 + us + uq;
                    xzp = __ldg(&g_xg[xo]);
                    xrp = __ldg(&g_xg[xo + UU]);
                    xhp = __ldg(&g_xg[xo + 2 * UU]);
                }
            }

            // ---- hg = next @ Wrec via k-paired FFMA2 (192 threads) ----
            if (tid < 192) {
                const ulonglong2* wrow = (const ulonglong2*)Wc + cc * (WROW / 4);
                const ulonglong2* a0r  = (const ulonglong2*)Ab + (2 * bq)     * (AROW / 4);
                const ulonglong2* a1r  = (const ulonglong2*)Ab + (2 * bq + 1) * (AROW / 4);
                ull acc00 = 0ull, acc01 = 0ull, acc10 = 0ull, acc11 = 0ull;
                #pragma unroll 8
                for (int m2 = 0; m2 < 64; ++m2) {
                    ulonglong2 w  = wrow[m2];
                    ulonglong2 a0 = a0r[m2];
                    ulonglong2 a1 = a1r[m2];
                    FMA2(acc00, a0.x, w.x);
                    FMA2(acc01, a0.y, w.y);
                    FMA2(acc10, a1.x, w.x);
                    FMA2(acc11, a1.y, w.y);
                }
                ADD2(acc00, acc01);
                ADD2(acc10, acc11);
                float p0, p1, q0, q1;
                unpack2(acc00, p0, p1);
                unpack2(acc10, q0, q1);
                Gh[(2 * bq)     * 96 + cc] = (p0 + p1) + bh;
                Gh[(2 * bq + 1) * 96 + cc] = (q0 + q1) + bh;
            }
            __syncthreads();

            // ---- gates + output (4b x 32u = 128 threads); stage next cond ----
            if (tid < 128) {
                const int uq = tid & 31, bb = tid >> 5;
                float hz = Gh[bb * 96 + uq];
                float hr = Gh[bb * 96 + 32 + uq];
                float hh = Gh[bb * 96 + 64 + uq];
                float z  = 1.0f / (1.0f + __expf(-(xz + hz)));
                float r  = 1.0f / (1.0f + __expf(-(xr + hr)));
                float hc = tanh_fast(xh + r * hh);
                float h  = Ab[bb * AROW + us + uq];   // next_state
                out[((size_t)(b0 + bb) * TT + i) * UU + us + uq]
                    = z * h + (1.0f - z) * hc;
                if ((tid >> 2) < lnext) CsmNxt[tid] = cnext;
            }
            xz = xzp; xr = xrp; xh = xhp;
            cluster_sync();
        }
    }
}

extern "C" void kernel_launch(void* const* d_in, const int* in_sizes, int n_in,
                              void* d_out, int out_size) {
    const float* x    = (const float*)d_in[0];
    const float* cond = (const float*)d_in[1];
    const float* Win  = (const float*)d_in[2];
    const float* Wrec = (const float*)d_in[3];
    const float* bias = (const float*)d_in[4];
    float* out = (float*)d_out;

    const int smem_bytes = SMEM_F * sizeof(float);
    static bool attr_set = false;
    if (!attr_set) {
        cudaFuncSetAttribute(dag_rnn_kernel,
                             cudaFuncAttributeMaxDynamicSharedMemorySize, smem_bytes);
        attr_set = true;
    }
    dag_rnn_kernel<<<NBLK, TPB, smem_bytes>>>(x, cond, Win, Wrec, bias, out);
}

// round 16
// speedup vs baseline: 1.4107x; 1.4107x over previous
#include <cuda_runtime.h>
#include <math.h>

typedef unsigned long long ull;

#define TT   512
#define BBAT 64
#define DD   128
#define UU   256
#define G3   768
#define NBLK 128
#define TPB  256
#define CH   8
#define NGRP 32
#define GBLK 4            // blocks per group (group = 2 batches, u split 4 ways)
#define WROW 260          // Wc row stride in floats
#define AROW 260          // Ab row stride in floats

// ---------------- device scratch ----------------
__device__ float g_xg[(size_t)BBAT * TT * G3];   // x @ W_in + bias0
__device__ float g_basep[2][BBAT][CH][UU];       // chunk-base partials (2 j-halves)
// per-group barrier state, 256B-strided
__device__ unsigned g_barcnt[NGRP * 64];
__device__ volatile unsigned g_bargen[NGRP * 64];

// packed f32x2 helpers (Blackwell; ptxas never emits FFMA2 from C++)
#define FMA2(acc, a, b) \
    asm("fma.rn.f32x2 %0, %1, %2, %0;" : "+l"(acc) : "l"(a), "l"(b))
#define ADD2(acc, a) \
    asm("add.rn.f32x2 %0, %1, %0;" : "+l"(acc) : "l"(a))
__device__ __forceinline__ void unpack2(ull v, float& x, float& y) {
    asm("mov.b64 {%0, %1}, %2;" : "=f"(x), "=f"(y) : "l"(v));
}
__device__ __forceinline__ float tanh_fast(float v) {
    float y; asm("tanh.approx.f32 %0, %1;" : "=f"(y) : "f"(v)); return y;
}

// Group barrier (R13-proven): 4 CTAs/group, all resident. Per-thread
// __threadfence (gpu-scope release) before arrival; central atomic count;
// single-leader nanosleep spin; fence on wake. Cross-block data via __ldcg.
__device__ __forceinline__ void group_sync(int gid) {
    __threadfence();
    __syncthreads();
    if (threadIdx.x == 0) {
        const int sdx = gid * 64;
        unsigned g = g_bargen[sdx];
        if (atomicAdd(&g_barcnt[sdx], 1u) == GBLK - 1) {
            atomicExch(&g_barcnt[sdx], 0u);
            __threadfence();
            g_bargen[sdx] = g + 1;
        } else {
            while (g_bargen[sdx] == g) { __nanosleep(32); }
        }
        __threadfence();
    }
    __syncthreads();
}

// smem layout (float offsets)
#define WC_OFF   0        // Wc: 192 cols x 260 f (col-major, k contiguous) = 49920 f
#define AB_OFF   49920    // Ab: 2 batches x 260 f (next_state rows)
#define BIG_OFF  50440    // 4096 f union: stage0 As (32x128) / chunk Hs (16x256)
#define CS_OFF   54536    // 128 f chunk cond tile (16 j x 8 l)
#define CSM_OFF  54664    // 32 f per-step cond stage (double-buffered 2x16)
#define GH_OFF   54696    // 384 f h-side preactivations [2][192]
#define SMEM_F   55080    // 220320 B

__global__ void __launch_bounds__(TPB, 1) dag_rnn_kernel(
    const float* __restrict__ x,     // (B,T,D)
    const float* __restrict__ cond,  // (B,T,T)
    const float* __restrict__ Win,   // (D,3U)
    const float* __restrict__ Wrec,  // (U,3U)
    const float* __restrict__ bias,  // (2,3U)
    float* __restrict__ out)         // (B,T,U) == H storage
{
    extern __shared__ __align__(16) float smem[];
    float* Wc  = smem + WC_OFF;           // [cc][k], stride WROW
    float* Ab  = smem + AB_OFF;           // [bb][k], stride AROW
    float* BIG = smem + BIG_OFF;
    float* Cs  = smem + CS_OFF;
    float* Csm = smem + CSM_OFF;          // 2 x 16
    float* Gh  = smem + GH_OFF;           // [bb][cc]

    const int tid = threadIdx.x;
    const int blk = blockIdx.x;
    const int gid = blk >> 2;          // group (2 batches)
    const int s   = blk & 3;           // u-slice within group

    const int b0 = gid * 2;            // first batch of group
    const int us = 64 * s;             // u-slice origin (64 u per block)

    // GEMM identity (tid<192): thread = column cc (192 = 3 gates x 64 u),
    // accumulates BOTH batches (k-paired f32x2, 2 rows)
    const int cc = tid;                // 0..191 (only tid<192 used)
    const int gcol = (cc >> 6) * UU + us + (cc & 63);
    float bh = 0.f;
    if (tid < 192) bh = bias[G3 + gcol];

    // ---- preload Wrec slice col-major: Wc[cc*WROW + k] (192 x 256) ----
    for (int idx = tid; idx < 192 * UU; idx += TPB) {
        int ccc = idx >> 8, k = idx & 255;
        int colc = (ccc >> 6) * UU + us + (ccc & 63);
        Wc[ccc * WROW + k] = Wrec[(size_t)k * G3 + colc];
    }

    // ================= stage 0: g_xg = x @ Win + bias0 =================
    // block rows [blk*256, blk*256+256): group g's 4 blocks = batches 2g,2g+1
    {
        float* As = BIG;                       // 32 x 128 = 4096 f
        const float bz  = bias[tid];
        const float br  = bias[UU + tid];
        const float bhh = bias[2 * UU + tid];
        const int row0 = blk * 256;
        for (int rt = 0; rt < 8; ++rt) {
            const int rbase = row0 + rt * 32;
            __syncthreads();
            for (int idx = tid; idx < 32 * DD; idx += TPB)
                As[idx] = x[(size_t)rbase * DD + idx];
            __syncthreads();
            for (int rs = 0; rs < 4; ++rs) {
                float a0[8], a1[8], a2[8];
                #pragma unroll
                for (int r = 0; r < 8; ++r) { a0[r] = 0.f; a1[r] = 0.f; a2[r] = 0.f; }
                const float* asr = As + (rs * 8) * DD;
                #pragma unroll 4
                for (int k = 0; k < DD; ++k) {
                    float w0 = __ldg(&Win[(size_t)k * G3 + tid]);
                    float w1 = __ldg(&Win[(size_t)k * G3 + UU + tid]);
                    float w2 = __ldg(&Win[(size_t)k * G3 + 2 * UU + tid]);
                    #pragma unroll
                    for (int r = 0; r < 8; ++r) {
                        float a = asr[r * DD + k];
                        a0[r] += a * w0; a1[r] += a * w1; a2[r] += a * w2;
                    }
                }
                #pragma unroll
                for (int r = 0; r < 8; ++r) {
                    size_t ro = (size_t)(rbase + rs * 8 + r) * G3;
                    g_xg[ro + tid]          = a0[r] + bz;
                    g_xg[ro + UU + tid]     = a1[r] + br;
                    g_xg[ro + 2 * UU + tid] = a2[r] + bhh;
                }
            }
        }
    }
    group_sync(gid);

    const float invT = 1.0f / (float)TT;

    // gate-input registers (tid<128: bb = tid>>6, uq = tid&63), one step ahead
    float xz = 0.f, xr = 0.f, xh = 0.f;
    if (tid < 128) {
        const int uq = tid & 63, bb2 = tid >> 6;
        const size_t xo = ((size_t)(b0 + bb2) * TT + 0) * G3 + us + uq;
        xz = __ldg(&g_xg[xo]);
        xr = __ldg(&g_xg[xo + UU]);
        xh = __ldg(&g_xg[xo + 2 * UU]);
    }

    for (int c0 = 0; c0 < TT; c0 += CH) {
        // ---------- chunk-base GEMM: 2 group batches x 2 j-halves ----------
        if (c0 > 0) {
            float* Hs = BIG;                   // 16 x 256 tile
            const int cb   = b0 + (s >> 1);    // batch for this block
            const int jh   = s & 1;            // j-half
            const int kb   = c0 >> 1;
            const int jbeg = jh * kb;
            const float* hrow = out  + ((size_t)cb * TT + jbeg) * UU;
            const float* crow = cond + ((size_t)cb * TT + c0) * TT + jbeg;

            float acc[2][8];
            #pragma unroll
            for (int a = 0; a < 2; ++a)
                #pragma unroll
                for (int q = 0; q < 8; ++q) acc[a][q] = 0.f;

            const int lg = tid >> 5;
            const int ug = tid & 31;

            for (int jt = 0; jt < kb; jt += 16) {
                const int jn = (kb - jt < 16) ? (kb - jt) : 16;
                __syncthreads();
                for (int idx = tid; idx < jn * UU; idx += TPB)
                    Hs[idx] = __ldcg(&hrow[(size_t)jt * UU + idx]);
                {
                    int l = tid >> 5, jj = tid & 31;
                    if (jj < jn)
                        Cs[jj * CH + l] = __ldg(&crow[(size_t)l * TT + jt + jj]);
                }
                __syncthreads();
                if (tid < 128) {
                    for (int jj = 0; jj < jn; ++jj) {
                        float cv0 = Cs[jj * CH + lg];
                        float cv1 = Cs[jj * CH + lg + 4];
                        const float4* h4 = (const float4*)&Hs[jj * UU + ug * 8];
                        float4 ha = h4[0], hb2 = h4[1];
                        acc[0][0] += cv0 * ha.x;  acc[0][1] += cv0 * ha.y;
                        acc[0][2] += cv0 * ha.z;  acc[0][3] += cv0 * ha.w;
                        acc[0][4] += cv0 * hb2.x; acc[0][5] += cv0 * hb2.y;
                        acc[0][6] += cv0 * hb2.z; acc[0][7] += cv0 * hb2.w;
                        acc[1][0] += cv1 * ha.x;  acc[1][1] += cv1 * ha.y;
                        acc[1][2] += cv1 * ha.z;  acc[1][3] += cv1 * ha.w;
                        acc[1][4] += cv1 * hb2.x; acc[1][5] += cv1 * hb2.y;
                        acc[1][6] += cv1 * hb2.z; acc[1][7] += cv1 * hb2.w;
                    }
                }
            }
            if (tid < 128) {
                #pragma unroll
                for (int li = 0; li < 2; ++li) {
                    const int l = lg + li * 4;
                    float* dst = &g_basep[jh][cb][l][ug * 8];
                    ((float4*)dst)[0] = make_float4(acc[li][0], acc[li][1],
                                                    acc[li][2], acc[li][3]);
                    ((float4*)dst)[1] = make_float4(acc[li][4], acc[li][5],
                                                    acc[li][6], acc[li][7]);
                }
            }
            group_sync(gid);
        }

        // ---------------- sequential steps within chunk ----------------
        for (int l = 0; l < CH; ++l) {
            const int i = c0 + l;
            const int lnext = (l < CH - 1) ? (l + 1) : 0;
            float* CsmCur = Csm + (l & 1) * 16;
            float* CsmNxt = Csm + ((l + 1) & 1) * 16;

            // ---- phase A: full next_state for 2 batches (thread = u) ----
            {
                const int u = tid;             // 0..255
                float acc[2];
                if (c0 > 0) {
                    #pragma unroll
                    for (int bb = 0; bb < 2; ++bb)
                        acc[bb] = __ldcg(&g_basep[0][b0 + bb][l][u])
                                + __ldcg(&g_basep[1][b0 + bb][l][u]);
                } else {
                    acc[0] = 0.f; acc[1] = 0.f;
                }
                for (int jj = 0; jj < l; ++jj) {
                    #pragma unroll
                    for (int bb = 0; bb < 2; ++bb) {
                        float cv = CsmCur[jj * 2 + bb];
                        acc[bb] += cv * __ldcg(
                            &out[((size_t)(b0 + bb) * TT + c0 + jj) * UU + u]);
                    }
                }
                Ab[u]        = acc[0] * invT;
                Ab[AROW + u] = acc[1] * invT;
            }
            __syncthreads();

            // ---- prefetch next step's cond + gate inputs ----
            float cnext = 0.f, xzp = 0.f, xrp = 0.f, xhp = 0.f;
            if (tid < 128) {
                const int jj = tid >> 1, bb = tid & 1;
                if (jj < lnext)
                    cnext = __ldg(&cond[((size_t)(b0 + bb) * TT + (i + 1)) * TT
                                        + c0 + jj]);
                if (i + 1 < TT) {
                    const int uq = tid & 63, bb2 = tid >> 6;
                    const size_t xo = ((size_t)(b0 + bb2) * TT + (i + 1)) * G3 + us + uq;
                    xzp = __ldg(&g_xg[xo]);
                    xrp = __ldg(&g_xg[xo + UU]);
                    xhp = __ldg(&g_xg[xo + 2 * UU]);
                }
            }

            // ---- hg = next @ Wrec via k-paired FFMA2 (192 threads, 1 col each) ----
            if (tid < 192) {
                const ulonglong2* wrow = (const ulonglong2*)Wc + cc * (WROW / 4);
                const ulonglong2* a0r  = (const ulonglong2*)Ab;
                const ulonglong2* a1r  = (const ulonglong2*)Ab + (AROW / 4);
                ull acc00 = 0ull, acc01 = 0ull, acc10 = 0ull, acc11 = 0ull;
                #pragma unroll 8
                for (int m2 = 0; m2 < 64; ++m2) {
                    ulonglong2 w  = wrow[m2];
                    ulonglong2 a0 = a0r[m2];
                    ulonglong2 a1 = a1r[m2];
                    FMA2(acc00, a0.x, w.x);
                    FMA2(acc01, a0.y, w.y);
                    FMA2(acc10, a1.x, w.x);
                    FMA2(acc11, a1.y, w.y);
                }
                ADD2(acc00, acc01);
                ADD2(acc10, acc11);
                float p0, p1, q0, q1;
                unpack2(acc00, p0, p1);
                unpack2(acc10, q0, q1);
                Gh[cc]       = (p0 + p1) + bh;
                Gh[192 + cc] = (q0 + q1) + bh;
            }
            __syncthreads();

            // ---- gates + output (2b x 64u = 128 threads); stage next cond ----
            if (tid < 128) {
                const int uq = tid & 63, bb = tid >> 6;
                float hz = Gh[bb * 192 + uq];
                float hr = Gh[bb * 192 + 64 + uq];
                float hh = Gh[bb * 192 + 128 + uq];
                float z  = 1.0f / (1.0f + __expf(-(xz + hz)));
                float r  = 1.0f / (1.0f + __expf(-(xr + hr)));
                float hc = tanh_fast(xh + r * hh);
                float h  = Ab[bb * AROW + us + uq];   // next_state
                out[((size_t)(b0 + bb) * TT + i) * UU + us + uq]
                    = z * h + (1.0f - z) * hc;
                if ((tid >> 1) < lnext) CsmNxt[tid] = cnext;
            }
            xz = xzp; xr = xrp; xh = xhp;
            group_sync(gid);
        }
    }
}

extern "C" void kernel_launch(void* const* d_in, const int* in_sizes, int n_in,
                              void* d_out, int out_size) {
    const float* x    = (const float*)d_in[0];
    const float* cond = (const float*)d_in[1];
    const float* Win  = (const float*)d_in[2];
    const float* Wrec = (const float*)d_in[3];
    const float* bias = (const float*)d_in[4];
    float* out = (float*)d_out;

    const int smem_bytes = SMEM_F * sizeof(float);
    static bool attr_set = false;
    if (!attr_set) {
        cudaFuncSetAttribute(dag_rnn_kernel,
                             cudaFuncAttributeMaxDynamicSharedMemorySize, smem_bytes);
        attr_set = true;
    }
    dag_rnn_kernel<<<NBLK, TPB, smem_bytes>>>(x, cond, Win, Wrec, bias, out);
}